// round 2
// baseline (speedup 1.0000x reference)
#include <cuda_runtime.h>
#include <cuda_bf16.h>
#include <math.h>

#define BB   4096
#define NN   32
#define DIN  256
#define HH   256
#define RR   3
#define VDECAY 0.7f

// ---------------- device scratch (no runtime allocation allowed) ----------------
// W_f transposed:  layout [r][h/4][g][4]  => index ((r*64 + h4)*256 + g)*4 + e
__device__ float g_WfT[RR * HH * HH];
// Gate weights transposed: [gate][k][g], gate 0=i,1=o,2=u
__device__ float g_WgT[3 * 512 * HH];
// combined [b][512] = [input_vec | child_h_sum]
__device__ float g_comb[BB * 512];
// child_c_sum [b][256]
__device__ float g_csum[BB * HH];

// ---------------- prep: transposes ----------------
__global__ void prep_kernel(const float* __restrict__ Wf,
                            const float* __restrict__ Wi,
                            const float* __restrict__ Wo,
                            const float* __restrict__ Wu) {
    int idx = blockIdx.x * blockDim.x + threadIdx.x;
    const int NF = RR * HH * HH;        // 196608
    const int NG = 3 * 512 * HH;        // 393216
    if (idx < NF) {
        // dst idx = ((r*64 + h4)*256 + g)*4 + e
        int e = idx & 3;
        int t = idx >> 2;
        int g = t & 255; t >>= 8;
        int h4 = t & 63;
        int r  = t >> 6;
        int h  = h4 * 4 + e;
        g_WfT[idx] = Wf[(r * HH + g) * HH + h];
    } else if (idx < NF + NG) {
        int j = idx - NF;
        int g = j & 255;
        int t = j >> 8;
        int k = t & 511;
        int gate = t >> 9;
        const float* W = (gate == 0) ? Wi : ((gate == 1) ? Wo : Wu);
        g_WgT[j] = W[g * 512 + k];
    }
}

// ---------------- kernel 1: per-batch tree aggregation ----------------
// grid = 4096 blocks (one per batch), 256 threads.
// dynamic smem: sh_ch[32][260] + sh_facc[32][256]
#define CH_STRIDE 260
#define SMEM1 ((32 * CH_STRIDE + 32 * 256) * 4)

__global__ __launch_bounds__(256) void tree_kernel(
    const float* __restrict__ input_vec,
    const float* __restrict__ child_h,
    const float* __restrict__ child_c,
    const int*   __restrict__ relation_ids,
    const int*   __restrict__ virtual_mask,   // int32 (harness has no bool dtype)
    const float* __restrict__ rel_emb,
    const float* __restrict__ b_f,
    const float* __restrict__ w_att,
    const float* __restrict__ b_att)
{
    extern __shared__ float sm[];
    float* sh_ch   = sm;                     // [32][CH_STRIDE]
    float* sh_facc = sm + 32 * CH_STRIDE;    // [32][256], column g private to thread g

    __shared__ int   sh_rid[NN], sh_perm[NN], sh_rid_s[NN], sh_bounds[4];
    __shared__ float sh_decay[NN], sh_decay_s[NN], sh_score[NN], sh_attn[NN];

    const int b   = blockIdx.x;
    const int tid = threadIdx.x;
    const int lane = tid & 31;
    const int warp = tid >> 5;

    // ---- load relation ids / masks ----
    if (tid < NN) {
        int r = relation_ids[b * NN + tid];
        sh_rid[tid]   = r;
        sh_decay[tid] = virtual_mask[b * NN + tid] ? VDECAY : 1.0f;
    }
    __syncthreads();

    // ---- sort children by relation (thread 0, tiny) ----
    if (tid == 0) {
        int cnt[3] = {0, 0, 0};
        for (int n = 0; n < NN; n++) cnt[sh_rid[n]]++;
        int off[3];
        off[0] = 0; off[1] = cnt[0]; off[2] = cnt[0] + cnt[1];
        sh_bounds[0] = 0; sh_bounds[1] = off[1]; sh_bounds[2] = off[2]; sh_bounds[3] = NN;
        for (int n = 0; n < NN; n++) {
            int r = sh_rid[n];
            int p = off[r]++;
            sh_perm[p]    = n;
            sh_rid_s[p]   = r;
            sh_decay_s[p] = sh_decay[n];
        }
    }
    __syncthreads();

    // ---- load decayed child_h tile in sorted order (coalesced over h) ----
    {
        const float* chb = child_h + (size_t)b * NN * HH;
        for (int idx = tid; idx < NN * HH; idx += 256) {
            int p = idx >> 8;
            int h = idx & 255;
            sh_ch[p * CH_STRIDE + h] = chb[sh_perm[p] * HH + h] * sh_decay_s[p];
        }
    }
    __syncthreads();

    // ---- attention scores: each warp handles 4 children ----
    {
        float batt = b_att[0];
        for (int c = 0; c < 4; c++) {
            int p = warp * 4 + c;
            int r = sh_rid_s[p];
            float s = 0.0f;
            #pragma unroll
            for (int j = 0; j < 8; j++) {
                int h = j * 32 + lane;
                s = fmaf(rel_emb[r * HH + h] + sh_ch[p * CH_STRIDE + h], w_att[h], s);
            }
            #pragma unroll
            for (int off = 16; off; off >>= 1)
                s += __shfl_xor_sync(0xffffffffu, s, off);
            if (lane == 0) sh_score[p] = s + batt;
        }
    }
    __syncthreads();

    // ---- softmax over 32 children (warp 0) ----
    if (warp == 0) {
        float v = sh_score[lane];
        float m = v;
        #pragma unroll
        for (int off = 16; off; off >>= 1)
            m = fmaxf(m, __shfl_xor_sync(0xffffffffu, m, off));
        float e = expf(v - m);
        float s = e;
        #pragma unroll
        for (int off = 16; off; off >>= 1)
            s += __shfl_xor_sync(0xffffffffu, s, off);
        sh_attn[lane] = e / s;
    }
    __syncthreads();

    const int g = tid;

    // ---- child_h_sum + combined vector ----
    {
        float hs = 0.0f;
        #pragma unroll
        for (int p = 0; p < NN; p++)
            hs = fmaf(sh_attn[p], sh_ch[p * CH_STRIDE + g], hs);
        g_comb[b * 512 + 256 + g] = hs;
        g_comb[b * 512 + g]       = input_vec[b * DIN + g];
    }

    // ---- relation-routed forget matvec, h-outer with register-cached weights ----
    #pragma unroll
    for (int p = 0; p < NN; p++) sh_facc[p * 256 + g] = 0.0f;

    const float4* wf4 = (const float4*)g_WfT;
    for (int r = 0; r < RR; r++) {
        int p0 = sh_bounds[r], p1 = sh_bounds[r + 1];
        if (p0 >= p1) continue;
        #pragma unroll 1
        for (int hb = 0; hb < 8; hb++) {
            float4 w[8];
            #pragma unroll
            for (int j = 0; j < 8; j++)
                w[j] = wf4[(r * 64 + hb * 8 + j) * 256 + g];
            for (int p = p0; p < p1; ++p) {
                const float4* cp = (const float4*)&sh_ch[p * CH_STRIDE + hb * 32];
                float4 c0 = cp[0], c1 = cp[1], c2 = cp[2], c3 = cp[3];
                float4 c4 = cp[4], c5 = cp[5], c6 = cp[6], c7 = cp[7];
                float s0 = 0.f, s1 = 0.f, s2 = 0.f, s3 = 0.f;
                s0 = fmaf(c0.x, w[0].x, s0); s0 = fmaf(c0.y, w[0].y, s0);
                s0 = fmaf(c0.z, w[0].z, s0); s0 = fmaf(c0.w, w[0].w, s0);
                s1 = fmaf(c1.x, w[1].x, s1); s1 = fmaf(c1.y, w[1].y, s1);
                s1 = fmaf(c1.z, w[1].z, s1); s1 = fmaf(c1.w, w[1].w, s1);
                s2 = fmaf(c2.x, w[2].x, s2); s2 = fmaf(c2.y, w[2].y, s2);
                s2 = fmaf(c2.z, w[2].z, s2); s2 = fmaf(c2.w, w[2].w, s2);
                s3 = fmaf(c3.x, w[3].x, s3); s3 = fmaf(c3.y, w[3].y, s3);
                s3 = fmaf(c3.z, w[3].z, s3); s3 = fmaf(c3.w, w[3].w, s3);
                s0 = fmaf(c4.x, w[4].x, s0); s0 = fmaf(c4.y, w[4].y, s0);
                s0 = fmaf(c4.z, w[4].z, s0); s0 = fmaf(c4.w, w[4].w, s0);
                s1 = fmaf(c5.x, w[5].x, s1); s1 = fmaf(c5.y, w[5].y, s1);
                s1 = fmaf(c5.z, w[5].z, s1); s1 = fmaf(c5.w, w[5].w, s1);
                s2 = fmaf(c6.x, w[6].x, s2); s2 = fmaf(c6.y, w[6].y, s2);
                s2 = fmaf(c6.z, w[6].z, s2); s2 = fmaf(c6.w, w[6].w, s2);
                s3 = fmaf(c7.x, w[7].x, s3); s3 = fmaf(c7.y, w[7].y, s3);
                s3 = fmaf(c7.z, w[7].z, s3); s3 = fmaf(c7.w, w[7].w, s3);
                sh_facc[p * 256 + g] += (s0 + s1) + (s2 + s3);
            }
        }
    }

    // ---- child_c_sum = sum_p (f_p + b_f) * cc_p ----
    {
        const float* ccb = child_c + (size_t)b * NN * HH + g;
        float cs = 0.0f;
        #pragma unroll
        for (int p = 0; p < NN; p++) {
            int r = sh_rid_s[p];
            int n = sh_perm[p];
            float ccv = ccb[n * HH] * sh_decay_s[p];
            cs = fmaf(sh_facc[p * 256 + g] + b_f[r * HH + g], ccv, cs);
        }
        g_csum[b * HH + g] = cs;
    }
}

// ---------------- kernel 2: gate GEMM (M=4096,K=512,N=3x256) + epilogue ----------------
// grid = 256 blocks (16 batches each), 256 threads (one output channel each)
__global__ __launch_bounds__(256) void gates_kernel(
    const float* __restrict__ b_i,
    const float* __restrict__ b_o,
    const float* __restrict__ b_u,
    float* __restrict__ out)
{
    __shared__ float sh_comb[16 * 512];
    const int b0  = blockIdx.x * 16;
    const int tid = threadIdx.x;

    for (int idx = tid; idx < 16 * 512; idx += 256)
        sh_comb[idx] = g_comb[b0 * 512 + idx];
    __syncthreads();

    const int g = tid;
    float ai[16], ao[16], au[16];
    #pragma unroll
    for (int m = 0; m < 16; m++) { ai[m] = 0.f; ao[m] = 0.f; au[m] = 0.f; }

    const float* wi = g_WgT;
    const float* wo = g_WgT + 512 * HH;
    const float* wu = g_WgT + 2 * 512 * HH;

    #pragma unroll 1
    for (int k4 = 0; k4 < 128; k4++) {
        int k = k4 * 4;
        float wi0 = wi[(k + 0) * HH + g], wi1 = wi[(k + 1) * HH + g];
        float wi2 = wi[(k + 2) * HH + g], wi3 = wi[(k + 3) * HH + g];
        float wo0 = wo[(k + 0) * HH + g], wo1 = wo[(k + 1) * HH + g];
        float wo2 = wo[(k + 2) * HH + g], wo3 = wo[(k + 3) * HH + g];
        float wu0 = wu[(k + 0) * HH + g], wu1 = wu[(k + 1) * HH + g];
        float wu2 = wu[(k + 2) * HH + g], wu3 = wu[(k + 3) * HH + g];
        #pragma unroll
        for (int m = 0; m < 16; m++) {
            float4 cm = *(const float4*)&sh_comb[m * 512 + k];
            ai[m] = fmaf(cm.x, wi0, fmaf(cm.y, wi1, fmaf(cm.z, wi2, fmaf(cm.w, wi3, ai[m]))));
            ao[m] = fmaf(cm.x, wo0, fmaf(cm.y, wo1, fmaf(cm.z, wo2, fmaf(cm.w, wo3, ao[m]))));
            au[m] = fmaf(cm.x, wu0, fmaf(cm.y, wu1, fmaf(cm.z, wu2, fmaf(cm.w, wu3, au[m]))));
        }
    }

    const float biv = b_i[g], bov = b_o[g], buv = b_u[g];
    #pragma unroll
    for (int m = 0; m < 16; m++) {
        int b = b0 + m;
        float iv = 1.0f / (1.0f + expf(-(ai[m] + biv)));
        float ov = 1.0f / (1.0f + expf(-(ao[m] + bov)));
        float uv = tanhf(au[m] + buv);
        float c  = fmaf(iv, uv, g_csum[b * HH + g]);
        float h  = ov * tanhf(c);
        out[b * HH + g]              = h;   // h first
        out[BB * HH + b * HH + g]    = c;   // then c
    }
}

// ---------------- launch ----------------
extern "C" void kernel_launch(void* const* d_in, const int* in_sizes, int n_in,
                              void* d_out, int out_size) {
    const float* input_vec = (const float*)d_in[0];
    const float* child_h   = (const float*)d_in[1];
    const float* child_c   = (const float*)d_in[2];
    const int*   rid       = (const int*)d_in[3];
    const int*   vmask     = (const int*)d_in[4];
    const float* rel_emb   = (const float*)d_in[5];
    const float* W_i = (const float*)d_in[6];
    const float* b_i = (const float*)d_in[7];
    const float* W_f = (const float*)d_in[8];
    const float* b_f = (const float*)d_in[9];
    const float* W_o = (const float*)d_in[10];
    const float* b_o = (const float*)d_in[11];
    const float* W_u = (const float*)d_in[12];
    const float* b_u = (const float*)d_in[13];
    const float* w_att = (const float*)d_in[14];
    const float* b_att = (const float*)d_in[15];
    float* out = (float*)d_out;

    cudaFuncSetAttribute(tree_kernel, cudaFuncAttributeMaxDynamicSharedMemorySize, SMEM1);

    prep_kernel<<<2304, 256>>>(W_f, W_i, W_o, W_u);
    tree_kernel<<<BB, 256, SMEM1>>>(input_vec, child_h, child_c, rid, vmask,
                                    rel_emb, b_f, w_att, b_att);
    gates_kernel<<<BB / 16, 256>>>(b_i, b_o, b_u, out);
}